// round 3
// baseline (speedup 1.0000x reference)
#include <cuda_runtime.h>
#include <math.h>

#define Nn 64
#define Cc 256
#define Tt 64
#define Vv 25
#define HID 16
#define NG 5
#define TV (Tt*Vv)   // 1600
#define TV4 (TV/4)   // 400 float4 per (n,c) slice

// Scratch (allowed: __device__ globals, no allocation)
__device__ float g_avg[Nn*Cc];
__device__ float g_max[Nn*Cc];
__device__ float g_gates[Nn*NG*Cc];

// Output joint permutation (concat order) and group id per output position
__constant__ int c_perm[Vv] = {0,1,2,3,20, 8,9,10,11,23,24, 16,17,18,19, 4,5,6,7,21,22, 12,13,14,15};
__constant__ int c_grp [Vv] = {0,0,0,0,0,  1,1,1,1,1,1,     2,2,2,2,     3,3,3,3,3,3,   4,4,4,4};
// Torso masks over v index: joints {0,1,2,3,20}
__constant__ float c_msum[Vv] = {1,1,1,1, 0,0,0,0, 0,0,0,0, 0,0,0,0, 0,0,0,0, 1, 0,0,0,0};
// Additive mask for max: 0 for torso, -inf otherwise  (val + (-inf) = -inf)
__constant__ float c_mneg[Vv] = {0,0,0,0,
    -__builtin_huge_valf(),-__builtin_huge_valf(),-__builtin_huge_valf(),-__builtin_huge_valf(),
    -__builtin_huge_valf(),-__builtin_huge_valf(),-__builtin_huge_valf(),-__builtin_huge_valf(),
    -__builtin_huge_valf(),-__builtin_huge_valf(),-__builtin_huge_valf(),-__builtin_huge_valf(),
    -__builtin_huge_valf(),-__builtin_huge_valf(),-__builtin_huge_valf(),-__builtin_huge_valf(),
    0,
    -__builtin_huge_valf(),-__builtin_huge_valf(),-__builtin_huge_valf(),-__builtin_huge_valf()};

// ---------------------------------------------------------------------------
// K1: per-(n,c) mean + max over torso joints across T, via fully-coalesced
// float4 reads of the entire 1600-float slice + constant masks.
// One block (256 thr) per (n,c). Also warms L2 with x for K3.
// ---------------------------------------------------------------------------
__global__ void __launch_bounds__(256) k_reduce(const float* __restrict__ x) {
    int nc  = blockIdx.x;
    int tid = threadIdx.x;
    const float4* p = reinterpret_cast<const float4*>(x + (size_t)nc * TV);

    float s = 0.f, m = -__builtin_huge_valf();
    #pragma unroll
    for (int r = 0; r < 2; r++) {
        int i = tid + r * 256;           // float4 index, 0..399
        if (i < TV4) {
            float4 v = p[i];
            int e = 4 * i;
            int v0 = e % 25, v1 = (e+1) % 25, v2 = (e+2) % 25, v3 = (e+3) % 25;
            s = fmaf(v.x, c_msum[v0], s);
            s = fmaf(v.y, c_msum[v1], s);
            s = fmaf(v.z, c_msum[v2], s);
            s = fmaf(v.w, c_msum[v3], s);
            m = fmaxf(m, v.x + c_mneg[v0]);
            m = fmaxf(m, v.y + c_mneg[v1]);
            m = fmaxf(m, v.z + c_mneg[v2]);
            m = fmaxf(m, v.w + c_mneg[v3]);
        }
    }
    // block reduce (8 warps)
    #pragma unroll
    for (int o = 16; o > 0; o >>= 1) {
        s += __shfl_xor_sync(0xFFFFFFFFu, s, o);
        m  = fmaxf(m, __shfl_xor_sync(0xFFFFFFFFu, m, o));
    }
    __shared__ float sh_s[8], sh_m[8];
    int warp = tid >> 5;
    if ((tid & 31) == 0) { sh_s[warp] = s; sh_m[warp] = m; }
    __syncthreads();
    if (tid == 0) {
        float S = 0.f, M = -__builtin_huge_valf();
        #pragma unroll
        for (int w = 0; w < 8; w++) { S += sh_s[w]; M = fmaxf(M, sh_m[w]); }
        g_avg[nc] = S * (1.0f / 320.0f);   // mean over T*5 = 320
        g_max[nc] = M;
    }
}

// ---------------------------------------------------------------------------
// K2: gates[n,f,c] = sigmoid( mlp_f(avg[n,:]) + mlp_f(max[n,:]) )
// One block per n, 256 threads.
// ---------------------------------------------------------------------------
__global__ void __launch_bounds__(256) k_mlp(
        const float* __restrict__ W1s, const float* __restrict__ b1s,
        const float* __restrict__ W2s, const float* __restrict__ b2s) {
    int n   = blockIdx.x;
    int tid = threadIdx.x;
    __shared__ float sA[Cc], sM[Cc], hs[NG*HID];

    sA[tid] = g_avg[n*Cc + tid];
    sM[tid] = g_max[n*Cc + tid];
    __syncthreads();

    int warp = tid >> 5, lane = tid & 31;
    for (int task = warp; task < NG*HID; task += 8) {
        const float* w1 = W1s + task * Cc;
        float a = 0.f, m = 0.f;
        #pragma unroll
        for (int k = 0; k < 8; k++) {
            float w = w1[lane + 32*k];
            a += sA[lane + 32*k] * w;
            m += sM[lane + 32*k] * w;
        }
        #pragma unroll
        for (int o = 16; o > 0; o >>= 1) {
            a += __shfl_xor_sync(0xFFFFFFFFu, a, o);
            m += __shfl_xor_sync(0xFFFFFFFFu, m, o);
        }
        if (lane == 0) {
            float b = b1s[task];
            hs[task] = fmaxf(a + b, 0.f) + fmaxf(m + b, 0.f);
        }
    }
    __syncthreads();

    int c = tid;
    #pragma unroll
    for (int f = 0; f < NG; f++) {
        const float4* w2 = reinterpret_cast<const float4*>(W2s + ((size_t)(f*Cc + c)) * HID);
        float acc = 2.0f * b2s[f*Cc + c];
        #pragma unroll
        for (int q = 0; q < 4; q++) {
            float4 w = w2[q];
            acc += hs[f*HID + 4*q + 0] * w.x;
            acc += hs[f*HID + 4*q + 1] * w.y;
            acc += hs[f*HID + 4*q + 2] * w.z;
            acc += hs[f*HID + 4*q + 3] * w.w;
        }
        g_gates[(n*NG + f)*Cc + c] = 1.0f / (1.0f + expf(-acc));
    }
}

// ---------------------------------------------------------------------------
// K3: out[n,c,t,vo] = x[n,c,t,perm[vo]] * gate[n, grp[vo], c]
// One block per (n,c). Coalesced float4 read (L2-resident from K1) into smem,
// permuted read from smem, coalesced streaming store (evict-first) so the
// output doesn't kick x out of L2.
// ---------------------------------------------------------------------------
__global__ void __launch_bounds__(256) k_apply(const float* __restrict__ x,
                                               float* __restrict__ out) {
    int nc = blockIdx.x;
    int n = nc >> 8, c = nc & 255;
    __shared__ float sx[TV];
    __shared__ float sg[NG];
    __shared__ int sp[Vv], sgr[Vv];
    int tid = threadIdx.x;
    if (tid < NG)  sg[tid]  = g_gates[(n*NG + tid)*Cc + c];
    if (tid < Vv) { sp[tid] = c_perm[tid]; sgr[tid] = c_grp[tid]; }

    const float4* px = reinterpret_cast<const float4*>(x + (size_t)nc * TV);
    float4* sx4 = reinterpret_cast<float4*>(sx);
    #pragma unroll
    for (int r = 0; r < 2; r++) {
        int i = tid + r * 256;
        if (i < TV4) sx4[i] = px[i];
    }
    __syncthreads();

    float* po = out + (size_t)nc * TV;
    #pragma unroll
    for (int r = 0; r < 7; r++) {
        int i = tid + r * 256;
        if (i < TV) {
            int t  = i / 25;
            int vo = i - t * 25;
            float val = sx[t * 25 + sp[vo]] * sg[sgr[vo]];
            __stcs(po + i, val);
        }
    }
}

extern "C" void kernel_launch(void* const* d_in, const int* in_sizes, int n_in,
                              void* d_out, int out_size) {
    const float* x   = (const float*)d_in[0];
    const float* W1s = (const float*)d_in[1];
    const float* b1s = (const float*)d_in[2];
    const float* W2s = (const float*)d_in[3];
    const float* b2s = (const float*)d_in[4];
    float* out = (float*)d_out;

    k_reduce<<<Nn*Cc, 256>>>(x);
    k_mlp<<<Nn, 256>>>(W1s, b1s, W2s, b2s);
    k_apply<<<Nn*Cc, 256>>>(x, out);
}

// round 4
// speedup vs baseline: 4.1005x; 4.1005x over previous
#include <cuda_runtime.h>
#include <math.h>

#define Nn 64
#define Cc 256
#define Tt 64
#define Vv 25
#define HID 16
#define NG 5
#define TV (Tt*Vv)   // 1600
#define TV4 (TV/4)   // 400 float4 per (n,c) slice

// Scratch (allowed: __device__ globals, no allocation)
__device__ float g_avg[Nn*Cc];
__device__ float g_max[Nn*Cc];
__device__ float g_gates[Nn*NG*Cc];

// Output joint permutation (concat order) and group id per output position
__constant__ int c_perm[Vv] = {0,1,2,3,20, 8,9,10,11,23,24, 16,17,18,19, 4,5,6,7,21,22, 12,13,14,15};
__constant__ int c_grp [Vv] = {0,0,0,0,0,  1,1,1,1,1,1,     2,2,2,2,     3,3,3,3,3,3,   4,4,4,4};

// ---------------------------------------------------------------------------
// K1: per-(n,c) mean + max over torso joints {0,1,2,3,20} across T.
// Fully-coalesced float4 read of the whole 1600-float slice; torso membership
// decided by ALU predicate (NO indexed constant loads — those serialize).
// One block (256 thr) per (n,c). Also warms L2 with x for K3.
// ---------------------------------------------------------------------------
__global__ void __launch_bounds__(256) k_reduce(const float* __restrict__ x) {
    int nc  = blockIdx.x;
    int tid = threadIdx.x;
    const float4* p = reinterpret_cast<const float4*>(x + (size_t)nc * TV);

    float s = 0.f, m = -__builtin_huge_valf();
    #pragma unroll
    for (int r = 0; r < 2; r++) {
        int i = tid + r * 256;             // float4 index, 0..399
        if (i < TV4) {
            float4 q = p[i];
            int e = 4 * i;
            int t = e / 25;                 // mul-hi, cheap
            int v = e - t * 25;             // v of first element, 0..24
            float vals[4] = {q.x, q.y, q.z, q.w};
            #pragma unroll
            for (int j = 0; j < 4; j++) {
                int vv = v + j;
                vv = (vv >= 25) ? vv - 25 : vv;
                bool tor = (vv < 4) | (vv == 20);
                float val = vals[j];
                s += tor ? val : 0.0f;
                m  = tor ? fmaxf(m, val) : m;
            }
        }
    }
    // block reduce (8 warps)
    #pragma unroll
    for (int o = 16; o > 0; o >>= 1) {
        s += __shfl_xor_sync(0xFFFFFFFFu, s, o);
        m  = fmaxf(m, __shfl_xor_sync(0xFFFFFFFFu, m, o));
    }
    __shared__ float sh_s[8], sh_m[8];
    int warp = tid >> 5;
    if ((tid & 31) == 0) { sh_s[warp] = s; sh_m[warp] = m; }
    __syncthreads();
    if (tid == 0) {
        float S = 0.f, M = -__builtin_huge_valf();
        #pragma unroll
        for (int w = 0; w < 8; w++) { S += sh_s[w]; M = fmaxf(M, sh_m[w]); }
        g_avg[nc] = S * (1.0f / 320.0f);   // mean over T*5 = 320
        g_max[nc] = M;
    }
}

// ---------------------------------------------------------------------------
// K2: gates[n,f,c] = sigmoid( mlp_f(avg[n,:]) + mlp_f(max[n,:]) )
// One block per n, 256 threads.
// ---------------------------------------------------------------------------
__global__ void __launch_bounds__(256) k_mlp(
        const float* __restrict__ W1s, const float* __restrict__ b1s,
        const float* __restrict__ W2s, const float* __restrict__ b2s) {
    int n   = blockIdx.x;
    int tid = threadIdx.x;
    __shared__ float sA[Cc], sM[Cc], hs[NG*HID];

    sA[tid] = g_avg[n*Cc + tid];
    sM[tid] = g_max[n*Cc + tid];
    __syncthreads();

    int warp = tid >> 5, lane = tid & 31;
    for (int task = warp; task < NG*HID; task += 8) {
        const float* w1 = W1s + task * Cc;
        float a = 0.f, m = 0.f;
        #pragma unroll
        for (int k = 0; k < 8; k++) {
            float w = w1[lane + 32*k];
            a += sA[lane + 32*k] * w;
            m += sM[lane + 32*k] * w;
        }
        #pragma unroll
        for (int o = 16; o > 0; o >>= 1) {
            a += __shfl_xor_sync(0xFFFFFFFFu, a, o);
            m += __shfl_xor_sync(0xFFFFFFFFu, m, o);
        }
        if (lane == 0) {
            float b = b1s[task];
            hs[task] = fmaxf(a + b, 0.f) + fmaxf(m + b, 0.f);
        }
    }
    __syncthreads();

    int c = tid;
    #pragma unroll
    for (int f = 0; f < NG; f++) {
        const float4* w2 = reinterpret_cast<const float4*>(W2s + ((size_t)(f*Cc + c)) * HID);
        float acc = 2.0f * b2s[f*Cc + c];
        #pragma unroll
        for (int q = 0; q < 4; q++) {
            float4 w = w2[q];
            acc += hs[f*HID + 4*q + 0] * w.x;
            acc += hs[f*HID + 4*q + 1] * w.y;
            acc += hs[f*HID + 4*q + 2] * w.z;
            acc += hs[f*HID + 4*q + 3] * w.w;
        }
        g_gates[(n*NG + f)*Cc + c] = 1.0f / (1.0f + expf(-acc));
    }
}

// ---------------------------------------------------------------------------
// K3: out[n,c,t,vo] = x[n,c,t,perm[vo]] * gate[n, grp[vo], c]
// One block per (n,c). Coalesced float4 read (L2-resident from K1) into smem,
// permuted read from smem, coalesced streaming store (evict-first) so the
// output doesn't kick x out of L2.
// ---------------------------------------------------------------------------
__global__ void __launch_bounds__(256) k_apply(const float* __restrict__ x,
                                               float* __restrict__ out) {
    int nc = blockIdx.x;
    int n = nc >> 8, c = nc & 255;
    __shared__ float sx[TV];
    __shared__ float sg[NG];
    __shared__ int sp[Vv], sgr[Vv];
    int tid = threadIdx.x;
    if (tid < NG)  sg[tid]  = g_gates[(n*NG + tid)*Cc + c];
    if (tid < Vv) { sp[tid] = c_perm[tid]; sgr[tid] = c_grp[tid]; }

    const float4* px = reinterpret_cast<const float4*>(x + (size_t)nc * TV);
    float4* sx4 = reinterpret_cast<float4*>(sx);
    #pragma unroll
    for (int r = 0; r < 2; r++) {
        int i = tid + r * 256;
        if (i < TV4) sx4[i] = px[i];
    }
    __syncthreads();

    float* po = out + (size_t)nc * TV;
    #pragma unroll
    for (int r = 0; r < 7; r++) {
        int i = tid + r * 256;
        if (i < TV) {
            int t  = i / 25;
            int vo = i - t * 25;
            float val = sx[t * 25 + sp[vo]] * sg[sgr[vo]];
            __stcs(po + i, val);
        }
    }
}

extern "C" void kernel_launch(void* const* d_in, const int* in_sizes, int n_in,
                              void* d_out, int out_size) {
    const float* x   = (const float*)d_in[0];
    const float* W1s = (const float*)d_in[1];
    const float* b1s = (const float*)d_in[2];
    const float* W2s = (const float*)d_in[3];
    const float* b2s = (const float*)d_in[4];
    float* out = (float*)d_out;

    k_reduce<<<Nn*Cc, 256>>>(x);
    k_mlp<<<Nn, 256>>>(W1s, b1s, W2s, b2s);
    k_apply<<<Nn*Cc, 256>>>(x, out);
}

// round 5
// speedup vs baseline: 4.7766x; 1.1649x over previous
#include <cuda_runtime.h>
#include <math.h>

#define Nn 64
#define Cc 256
#define Tt 64
#define Vv 25
#define HID 16
#define NG 5
#define TV (Tt*Vv)   // 1600
#define TV4 (TV/4)   // 400

// Scratch (allowed: __device__ globals, no allocation)
__device__ float g_avg[Nn*Cc];
__device__ float g_max[Nn*Cc];
__device__ float g_gates[Nn*NG*Cc];

// Gather tables live in __device__ global (L1-cached gather) — NOT __constant__,
// which serializes on divergent indices.
__device__ int d_perm[Vv] = {0,1,2,3,20, 8,9,10,11,23,24, 16,17,18,19, 4,5,6,7,21,22, 12,13,14,15};
__device__ int d_grp [Vv] = {0,0,0,0,0,  1,1,1,1,1,1,     2,2,2,2,     3,3,3,3,3,3,   4,4,4,4};

// ---------------------------------------------------------------------------
// K1: per-(n,c) mean + max over torso joints {0,1,2,3,20} across T.
// Threads tid<200 own a FIXED joint column v = tid%25 → torso predicate
// computed once; inner loop = 8 batched coalesced LDGs + predicated acc.
// Full-slice read also warms L2 with x for K3.
// ---------------------------------------------------------------------------
__global__ void __launch_bounds__(256) k_reduce(const float* __restrict__ x) {
    int nc  = blockIdx.x;
    int tid = threadIdx.x;

    float s = 0.f, m = -__builtin_huge_valf();
    if (tid < 200) {
        int row0 = tid / 25;            // unused, but keeps v exact
        int v = tid - row0 * 25;        // fixed joint for this thread
        bool tor = (v < 4) | (v == 20);
        const float* base = x + (size_t)nc * TV + tid;
        float vals[8];
        #pragma unroll
        for (int r = 0; r < 8; r++) vals[r] = base[200 * r];  // 1600 = 8*200
        if (tor) {
            #pragma unroll
            for (int r = 0; r < 8; r++) {
                s += vals[r];
                m  = fmaxf(m, vals[r]);
            }
        }
    }
    #pragma unroll
    for (int o = 16; o > 0; o >>= 1) {
        s += __shfl_xor_sync(0xFFFFFFFFu, s, o);
        m  = fmaxf(m, __shfl_xor_sync(0xFFFFFFFFu, m, o));
    }
    __shared__ float sh_s[8], sh_m[8];
    int warp = tid >> 5;
    if ((tid & 31) == 0) { sh_s[warp] = s; sh_m[warp] = m; }
    __syncthreads();
    if (tid == 0) {
        float S = 0.f, M = -__builtin_huge_valf();
        #pragma unroll
        for (int w = 0; w < 8; w++) { S += sh_s[w]; M = fmaxf(M, sh_m[w]); }
        g_avg[nc] = S * (1.0f / 320.0f);   // mean over T*5 = 320
        g_max[nc] = M;
    }
}

// ---------------------------------------------------------------------------
// K2: gates[n,f,c] = sigmoid( mlp_f(avg[n,:]) + mlp_f(max[n,:]) )
// One block per n, 256 threads.
// ---------------------------------------------------------------------------
__global__ void __launch_bounds__(256) k_mlp(
        const float* __restrict__ W1s, const float* __restrict__ b1s,
        const float* __restrict__ W2s, const float* __restrict__ b2s) {
    int n   = blockIdx.x;
    int tid = threadIdx.x;
    __shared__ float sA[Cc], sM[Cc], hs[NG*HID];

    sA[tid] = g_avg[n*Cc + tid];
    sM[tid] = g_max[n*Cc + tid];
    __syncthreads();

    int warp = tid >> 5, lane = tid & 31;
    for (int task = warp; task < NG*HID; task += 8) {
        const float* w1 = W1s + task * Cc;
        float a = 0.f, m = 0.f;
        #pragma unroll
        for (int k = 0; k < 8; k++) {
            float w = w1[lane + 32*k];
            a += sA[lane + 32*k] * w;
            m += sM[lane + 32*k] * w;
        }
        #pragma unroll
        for (int o = 16; o > 0; o >>= 1) {
            a += __shfl_xor_sync(0xFFFFFFFFu, a, o);
            m += __shfl_xor_sync(0xFFFFFFFFu, m, o);
        }
        if (lane == 0) {
            float b = b1s[task];
            hs[task] = fmaxf(a + b, 0.f) + fmaxf(m + b, 0.f);
        }
    }
    __syncthreads();

    int c = tid;
    #pragma unroll
    for (int f = 0; f < NG; f++) {
        const float4* w2 = reinterpret_cast<const float4*>(W2s + ((size_t)(f*Cc + c)) * HID);
        float acc = 2.0f * b2s[f*Cc + c];
        #pragma unroll
        for (int q = 0; q < 4; q++) {
            float4 w = w2[q];
            acc += hs[f*HID + 4*q + 0] * w.x;
            acc += hs[f*HID + 4*q + 1] * w.y;
            acc += hs[f*HID + 4*q + 2] * w.z;
            acc += hs[f*HID + 4*q + 3] * w.w;
        }
        g_gates[(n*NG + f)*Cc + c] = 1.0f / (1.0f + expf(-acc));
    }
}

// ---------------------------------------------------------------------------
// K3: out[n,c,t,vo] = x[n,c,t,perm[vo]] * gate[n, grp[vo], c]
// One block per (n,c). Coalesced float4 read (mostly L2-resident from K1)
// into smem; fused per-vo LUTs (perm index + gate value); float4 streaming
// stores so writes don't evict x from L2.
// ---------------------------------------------------------------------------
__global__ void __launch_bounds__(256) k_apply(const float* __restrict__ x,
                                               float* __restrict__ out) {
    int nc = blockIdx.x;
    int n = nc >> 8, c = nc & 255;
    __shared__ float sx[TV];
    __shared__ float sgv[Vv];   // gate value per OUTPUT joint position
    __shared__ int   spv[Vv];   // source joint per OUTPUT joint position
    int tid = threadIdx.x;
    if (tid < Vv) {
        int g = d_grp[tid];
        sgv[tid] = g_gates[(n*NG + g)*Cc + c];
        spv[tid] = d_perm[tid];
    }

    const float4* px = reinterpret_cast<const float4*>(x + (size_t)nc * TV);
    float4* sx4 = reinterpret_cast<float4*>(sx);
    #pragma unroll
    for (int r = 0; r < 2; r++) {
        int i = tid + r * 256;
        if (i < TV4) sx4[i] = px[i];
    }
    __syncthreads();

    float4* po4 = reinterpret_cast<float4*>(out + (size_t)nc * TV);
    #pragma unroll
    for (int r = 0; r < 2; r++) {
        int i4 = tid + r * 256;
        if (i4 < TV4) {
            int e   = 4 * i4;
            int t   = e / 25;
            int vo  = e - t * 25;
            int t25 = t * 25;
            float res[4];
            #pragma unroll
            for (int j = 0; j < 4; j++) {
                res[j] = sx[t25 + spv[vo]] * sgv[vo];
                vo++;
                if (vo == 25) { vo = 0; t25 += 25; }
            }
            __stcs(po4 + i4, make_float4(res[0], res[1], res[2], res[3]));
        }
    }
}

extern "C" void kernel_launch(void* const* d_in, const int* in_sizes, int n_in,
                              void* d_out, int out_size) {
    const float* x   = (const float*)d_in[0];
    const float* W1s = (const float*)d_in[1];
    const float* b1s = (const float*)d_in[2];
    const float* W2s = (const float*)d_in[3];
    const float* b2s = (const float*)d_in[4];
    float* out = (float*)d_out;

    k_reduce<<<Nn*Cc, 256>>>(x);
    k_mlp<<<Nn, 256>>>(W1s, b1s, W2s, b2s);
    k_apply<<<Nn*Cc, 256>>>(x, out);
}